// round 1
// baseline (speedup 1.0000x reference)
#include <cuda_runtime.h>
#include <cuda_bf16.h>

#define N_IN    16
#define FANIN   16
#define N_NODES 512
#define N_OUT   64
#define BATCH   32768
#define OUT_START (N_NODES - N_OUT)   // node 448

// Branch-free fast tanh: tanh(x) = 1 - 2/(exp(2x)+1)
// __expf -> FMUL + MUFU.EX2 ; __fdividef -> MUFU.RCP + FMUL.
// Handles large |x| gracefully (exp->inf => tanh->1, exp->0 => tanh->-1).
__device__ __forceinline__ float fast_tanh(float x) {
    float e = __expf(2.0f * x);
    return 1.0f - __fdividef(2.0f, e + 1.0f);
}

__global__ void __launch_bounds__(256, 1)
neat_forward_kernel(const float*  __restrict__ x,
                    const float4* __restrict__ w,     // [N_NODES][4] float4 = [N_NODES][16] f32
                    const float*  __restrict__ bias,
                    const float*  __restrict__ resp,
                    float*        __restrict__ out)   // [BATCH][N_OUT]
{
    __shared__ float4 w_sh[N_NODES * 4];   // 32 KB
    __shared__ float2 br_sh[N_NODES];      //  4 KB (bias, response)

    const int tid = threadIdx.x;
    for (int i = tid; i < N_NODES * 4; i += 256) w_sh[i] = w[i];
    for (int i = tid; i < N_NODES;     i += 256) br_sh[i] = make_float2(bias[i], resp[i]);
    __syncthreads();

    const int b = blockIdx.x * 256 + tid;      // batch element (grid covers BATCH exactly)

    // Circular window of the last 16 global node values, in registers.
    // Invariant: v[g & 15] holds the value at global index g for the 16 most
    // recent global indices. Node i reads global [i, i+16) and writes 16+i,
    // i.e. reads v[(j+t)&15] and overwrites v[j] where j = i & 15.
    float v[16];
    {
        const float4* xv = (const float4*)(x + (size_t)b * N_IN);
        #pragma unroll
        for (int q = 0; q < 4; q++) {
            float4 t = xv[q];
            v[4*q + 0] = t.x; v[4*q + 1] = t.y; v[4*q + 2] = t.z; v[4*q + 3] = t.w;
        }
    }

    float* outp = out + (size_t)b * N_OUT;

    #pragma unroll 1
    for (int g = 0; g < N_NODES / 16; g++) {
        #pragma unroll
        for (int j = 0; j < 16; j++) {
            const int node = g * 16 + j;
            const float4 w0 = w_sh[node * 4 + 0];
            const float4 w1 = w_sh[node * 4 + 1];
            const float4 w2 = w_sh[node * 4 + 2];
            const float4 w3 = w_sh[node * 4 + 3];
            const float2 br = br_sh[node];

            // 4-way split accumulators to shorten the FMA dependency chain.
            float a0 = v[(j + 0) & 15] * w0.x;
            float a1 = v[(j + 1) & 15] * w0.y;
            float a2 = v[(j + 2) & 15] * w0.z;
            float a3 = v[(j + 3) & 15] * w0.w;
            a0 = fmaf(v[(j + 4)  & 15], w1.x, a0);
            a1 = fmaf(v[(j + 5)  & 15], w1.y, a1);
            a2 = fmaf(v[(j + 6)  & 15], w1.z, a2);
            a3 = fmaf(v[(j + 7)  & 15], w1.w, a3);
            a0 = fmaf(v[(j + 8)  & 15], w2.x, a0);
            a1 = fmaf(v[(j + 9)  & 15], w2.y, a1);
            a2 = fmaf(v[(j + 10) & 15], w2.z, a2);
            a3 = fmaf(v[(j + 11) & 15], w2.w, a3);
            a0 = fmaf(v[(j + 12) & 15], w3.x, a0);
            a1 = fmaf(v[(j + 13) & 15], w3.y, a1);
            a2 = fmaf(v[(j + 14) & 15], w3.z, a2);
            a3 = fmaf(v[(j + 15) & 15], w3.w, a3);

            const float agg = (a0 + a1) + (a2 + a3) + br.x;
            const float res = fast_tanh(agg) * br.y;
            v[j] = res;

            if (g >= OUT_START / 16) {
                outp[(g - OUT_START / 16) * 16 + j] = res;
            }
        }
    }
}

extern "C" void kernel_launch(void* const* d_in, const int* in_sizes, int n_in,
                              void* d_out, int out_size) {
    const float*  x    = (const float*)d_in[0];   // [BATCH, 16]
    const float4* w    = (const float4*)d_in[1];  // [512, 16]
    const float*  bias = (const float*)d_in[2];   // [512]
    const float*  resp = (const float*)d_in[3];   // [512]
    // d_in[4] (src_idx) encodes the fixed sliding-window topology; baked in.
    float* out = (float*)d_out;                   // [BATCH, 64]

    neat_forward_kernel<<<BATCH / 256, 256>>>(x, w, bias, resp, out);
}

// round 2
// speedup vs baseline: 1.1459x; 1.1459x over previous
#include <cuda_runtime.h>
#include <cuda_bf16.h>

#define N_IN       16
#define FANIN      16
#define N_NODES    512
#define N_OUT      64
#define BATCH      32768
#define HALF_BATCH (BATCH / 2)
#define OUT_START  (N_NODES - N_OUT)   // node 448

#define THREADS    128
#define GRID       (HALF_BATCH / THREADS)   // 128 blocks

using u64 = unsigned long long;

// ---- packed f32x2 helpers (Blackwell sm_10x) ----
__device__ __forceinline__ u64 pack2(float lo, float hi) {
    u64 r; asm("mov.b64 %0, {%1, %2};" : "=l"(r) : "f"(lo), "f"(hi)); return r;
}
__device__ __forceinline__ void unpack2(u64 v, float& lo, float& hi) {
    asm("mov.b64 {%0, %1}, %2;" : "=f"(lo), "=f"(hi) : "l"(v));
}
__device__ __forceinline__ u64 fma2(u64 a, u64 b, u64 c) {
    u64 d; asm("fma.rn.f32x2 %0, %1, %2, %3;" : "=l"(d) : "l"(a), "l"(b), "l"(c)); return d;
}
__device__ __forceinline__ u64 mul2(u64 a, u64 b) {
    u64 d; asm("mul.rn.f32x2 %0, %1, %2;" : "=l"(d) : "l"(a), "l"(b)); return d;
}
__device__ __forceinline__ u64 add2(u64 a, u64 b) {
    u64 d; asm("add.rn.f32x2 %0, %1, %2;" : "=l"(d) : "l"(a), "l"(b)); return d;
}
// single-MUFU tanh (sm_75+): replaces FMUL+EX2+FADD+RCP+FFMA chain
__device__ __forceinline__ float tanh_approx(float x) {
    float y; asm("tanh.approx.f32 %0, %1;" : "=f"(y) : "f"(x)); return y;
}

// Dynamic smem layout (u64 units):
//   [0, 8192)            : duplicated packed weights  {w,w}  — 512 nodes x 16 taps (64 KB)
//   [8192, 8192+1024)    : per node {bias2, resp2} pairs (8 KB)
#define SMEM_W   0
#define SMEM_BR  (N_NODES * FANIN)
#define SMEM_U64 (N_NODES * FANIN + 2 * N_NODES)   // 9216 u64 = 72 KB

__global__ void __launch_bounds__(THREADS, 1)
neat_forward_f32x2(const float* __restrict__ x,
                   const float* __restrict__ w,      // [512][16]
                   const float* __restrict__ bias,   // [512]
                   const float* __restrict__ resp,   // [512]
                   float*       __restrict__ out)    // [BATCH][64]
{
    extern __shared__ __align__(16) u64 sh[];
    const int tid = threadIdx.x;

    // Duplicate weights/bias/resp into packed smem (broadcast-friendly).
    for (int i = tid; i < N_NODES * FANIN; i += THREADS) {
        float wv = w[i];
        sh[SMEM_W + i] = pack2(wv, wv);
    }
    for (int i = tid; i < N_NODES; i += THREADS) {
        float bv = bias[i], rv = resp[i];
        sh[SMEM_BR + 2 * i + 0] = pack2(bv, bv);
        sh[SMEM_BR + 2 * i + 1] = pack2(rv, rv);
    }
    __syncthreads();

    // Thread handles batch elements b0 and b1 = b0 + HALF_BATCH, packed as f32x2.
    const int b0 = blockIdx.x * THREADS + tid;
    const int b1 = b0 + HALF_BATCH;

    // Circular register window of the last 16 global node values (packed pairs).
    // v2[g & 15] holds global value g. Node i reads globals [i, i+16), writes 16+i:
    // with j = i & 15, it reads v2[(j+t)&15], t=0..15 (t=15 is the newest), writes v2[j].
    u64 v2[16];
    {
        const float4* x0 = (const float4*)(x + (size_t)b0 * N_IN);
        const float4* x1 = (const float4*)(x + (size_t)b1 * N_IN);
        #pragma unroll
        for (int q = 0; q < 4; q++) {
            float4 p = x0[q], s = x1[q];
            v2[4*q + 0] = pack2(p.x, s.x);
            v2[4*q + 1] = pack2(p.y, s.y);
            v2[4*q + 2] = pack2(p.z, s.z);
            v2[4*q + 3] = pack2(p.w, s.w);
        }
    }

    float* outp0 = out + (size_t)b0 * N_OUT;
    float* outp1 = out + (size_t)b1 * N_OUT;

    #pragma unroll 1
    for (int g = 0; g < N_NODES / 16; g++) {
        #pragma unroll
        for (int j = 0; j < 16; j++) {
            const int node = g * 16 + j;
            // 16 packed weights for this node as 8x LDS.128 (broadcast).
            const ulonglong2* wv = (const ulonglong2*)(sh + SMEM_W + node * FANIN);
            const ulonglong2 q0 = wv[0], q1 = wv[1], q2 = wv[2], q3 = wv[3];
            const ulonglong2 q4 = wv[4], q5 = wv[5], q6 = wv[6], q7 = wv[7];
            const ulonglong2 br = ((const ulonglong2*)(sh + SMEM_BR))[node]; // {bias2, resp2}

            // 4 split accumulators; the NEWEST tap (t=15, produced by node-1)
            // enters as the LAST fma of a3, and a3 joins the sum tree last,
            // minimizing the serial recurrence path.
            u64 a0 = mul2(v2[(j + 0)  & 15], q0.x);
            u64 a1 = mul2(v2[(j + 1)  & 15], q0.y);
            u64 a2 = mul2(v2[(j + 2)  & 15], q1.x);
            u64 a3 = mul2(v2[(j + 3)  & 15], q1.y);
            a0 = fma2(v2[(j + 4)  & 15], q2.x, a0);
            a1 = fma2(v2[(j + 5)  & 15], q2.y, a1);
            a2 = fma2(v2[(j + 6)  & 15], q3.x, a2);
            a3 = fma2(v2[(j + 7)  & 15], q3.y, a3);
            a0 = fma2(v2[(j + 8)  & 15], q4.x, a0);
            a1 = fma2(v2[(j + 9)  & 15], q4.y, a1);
            a2 = fma2(v2[(j + 10) & 15], q5.x, a2);
            a3 = fma2(v2[(j + 11) & 15], q5.y, a3);
            a0 = fma2(v2[(j + 12) & 15], q6.x, a0);
            a1 = fma2(v2[(j + 13) & 15], q6.y, a1);
            a2 = fma2(v2[(j + 14) & 15], q7.x, a2);
            a3 = fma2(v2[(j + 15) & 15], q7.y, a3);   // newest value, last

            const u64 s   = add2(a0, a1);
            const u64 t   = add2(a2, br.x);           // fold bias early
            const u64 u_  = add2(s, t);
            const u64 agg = add2(u_, a3);             // newest joins last

            float lo, hi;
            unpack2(agg, lo, hi);
            const float y0 = tanh_approx(lo);
            const float y1 = tanh_approx(hi);
            const u64 res = mul2(pack2(y0, y1), br.y);
            v2[j] = res;

            if (g >= OUT_START / 16) {
                float r0, r1;
                unpack2(res, r0, r1);
                const int o = node - OUT_START;
                outp0[o] = r0;
                outp1[o] = r1;
            }
        }
    }
}

extern "C" void kernel_launch(void* const* d_in, const int* in_sizes, int n_in,
                              void* d_out, int out_size) {
    const float* x    = (const float*)d_in[0];   // [BATCH, 16]
    const float* w    = (const float*)d_in[1];   // [512, 16]
    const float* bias = (const float*)d_in[2];   // [512]
    const float* resp = (const float*)d_in[3];   // [512]
    // d_in[4] (src_idx) is the fixed sliding-window topology; baked into indexing.
    float* out = (float*)d_out;                  // [BATCH, 64]

    const int smem_bytes = SMEM_U64 * (int)sizeof(u64);   // 73728 B > 48 KB -> opt in
    cudaFuncSetAttribute(neat_forward_f32x2,
                         cudaFuncAttributeMaxDynamicSharedMemorySize, smem_bytes);
    neat_forward_f32x2<<<GRID, THREADS, smem_bytes>>>(x, w, bias, resp, out);
}